// round 16
// baseline (speedup 1.0000x reference)
#include <cuda_runtime.h>
#include <cuda_bf16.h>
#include <math.h>

#define BB 32
#define EE 512
#define HH 1024
#define VV 32000
#define TT 64
#define START_TOK 1
#define F32_TINY 1.17549435e-38f
#define KTOT 1536
#define SPLITK 8
#define KSEG (KTOT / SPLITK)     // 192
#define LKC 32
#define NCHUNK_L (KSEG / LKC)    // 6
#define NCHUNK (HH / LKC)        // 32
#define MROWS 4096
// lstm mma smem map (4-stage, 128 rows)
#define SM_WHI 0
#define SM_WLO 40960
#define SM_HHI 81920
#define SM_HLO 92160
#define SM_PARTS 102400
#define SMEM_MMA 104448
// logits smem map (2-stage, 256 rows)
#define L2_TILEV 256
#define NBLK_LOG (VV / L2_TILEV)   // 125
#define S2_WHI 0                   // 2 stages x 256 x 80B = 40960
#define S2_WLO 40960
#define S2_HHI 81920               // 2 x 32 x 80B = 5120
#define S2_HLO 87040
#define S2_PARTS 92160
#define SMEM_LOG 94208

// ---------------- device scratch ----------------
__device__ __align__(16) float g_c[HH * BB];
__device__ __align__(16) float g_gpart[SPLITK * MROWS * BB];
__device__ unsigned long long g_best[TT * BB];
__device__ __align__(16) float g_stage[(size_t)BB * TT * VV]; // [b][t][v]
__device__ __align__(16) __nv_bfloat16 g_whi[(size_t)VV * HH];
__device__ __align__(16) __nv_bfloat16 g_wlo[(size_t)VV * HH];
__device__ __align__(16) __nv_bfloat16 g_wl_hi[(size_t)MROWS * KTOT];
__device__ __align__(16) __nv_bfloat16 g_wl_lo[(size_t)MROWS * KTOT];
__device__ __align__(16) __nv_bfloat16 g_xh_hi[BB * KTOT];
__device__ __align__(16) __nv_bfloat16 g_xh_lo[BB * KTOT];

// ---------------- threefry2x32 (JAX-compatible) ----------------
__device__ __forceinline__ void threefry2x32_dev(unsigned k0, unsigned k1,
                                                 unsigned x0, unsigned x1,
                                                 unsigned& o0, unsigned& o1) {
    unsigned ks2 = k0 ^ k1 ^ 0x1BD11BDAu;
    x0 += k0; x1 += k1;
#define TF_RND(r) { x0 += x1; x1 = __funnelshift_l(x1, x1, r); x1 ^= x0; }
    TF_RND(13) TF_RND(15) TF_RND(26) TF_RND(6)  x0 += k1;  x1 += ks2 + 1u;
    TF_RND(17) TF_RND(29) TF_RND(16) TF_RND(24) x0 += ks2; x1 += k0 + 2u;
    TF_RND(13) TF_RND(15) TF_RND(26) TF_RND(6)  x0 += k0;  x1 += k1 + 3u;
    TF_RND(17) TF_RND(29) TF_RND(16) TF_RND(24) x0 += k1;  x1 += ks2 + 4u;
    TF_RND(13) TF_RND(15) TF_RND(26) TF_RND(6)  x0 += ks2; x1 += k0 + 5u;
#undef TF_RND
    o0 = x0; o1 = x1;
}

__device__ __forceinline__ unsigned ford(float f) {
    unsigned u = __float_as_uint(f);
    return (u & 0x80000000u) ? ~u : (u | 0x80000000u);
}
__device__ __forceinline__ unsigned long long u64max(unsigned long long a,
                                                     unsigned long long b) {
    return a > b ? a : b;
}
__device__ __forceinline__ int decode_tok(unsigned long long key) {
    return (int)(0xFFFFFFFFu - (unsigned)(key & 0xFFFFFFFFull));
}

// ---------------- cp.async / ldsm / streaming-store helpers ----------------
__device__ __forceinline__ void cp_async16(unsigned dst, const void* src) {
    asm volatile("cp.async.cg.shared.global [%0], [%1], 16;"
                 :: "r"(dst), "l"(src) : "memory");
}
__device__ __forceinline__ void cp_commit() {
    asm volatile("cp.async.commit_group;" ::: "memory");
}
__device__ __forceinline__ void ldsm_x4(unsigned addr, unsigned* r) {
    asm volatile("ldmatrix.sync.aligned.m8n8.x4.shared.b16 {%0,%1,%2,%3}, [%4];"
                 : "=r"(r[0]), "=r"(r[1]), "=r"(r[2]), "=r"(r[3]) : "r"(addr));
}
__device__ __forceinline__ void stcs(float* p, float v) {
    asm volatile("st.global.cs.f32 [%0], %1;" :: "l"(p), "f"(v) : "memory");
}
#define MMA_BF16(c, a, b) \
    asm volatile("mma.sync.aligned.m16n8k16.row.col.f32.bf16.bf16.f32 " \
        "{%0,%1,%2,%3}, {%4,%5,%6,%7}, {%8,%9}, {%0,%1,%2,%3};" \
        : "+f"((c)[0]), "+f"((c)[1]), "+f"((c)[2]), "+f"((c)[3]) \
        : "r"((a)[0]), "r"((a)[1]), "r"((a)[2]), "r"((a)[3]), \
          "r"((b)[0]), "r"((b)[1]))

// ---------------- converts ----------------
__global__ __launch_bounds__(256) void convert_kernel(const float* __restrict__ W) {
    size_t i = ((size_t)blockIdx.x * 256 + threadIdx.x) * 4;
    float4 w = *(const float4*)(W + i);
    __nv_bfloat16 h0 = __float2bfloat16(w.x);
    __nv_bfloat16 h1 = __float2bfloat16(w.y);
    __nv_bfloat16 h2 = __float2bfloat16(w.z);
    __nv_bfloat16 h3 = __float2bfloat16(w.w);
    __nv_bfloat162 a, b, c, d;
    a.x = h0; a.y = h1; b.x = h2; b.y = h3;
    c.x = __float2bfloat16(w.x - __bfloat162float(h0));
    c.y = __float2bfloat16(w.y - __bfloat162float(h1));
    d.x = __float2bfloat16(w.z - __bfloat162float(h2));
    d.y = __float2bfloat16(w.w - __bfloat162float(h3));
    *(__nv_bfloat162*)(g_whi + i) = a;
    *(__nv_bfloat162*)(g_whi + i + 2) = b;
    *(__nv_bfloat162*)(g_wlo + i) = c;
    *(__nv_bfloat162*)(g_wlo + i + 2) = d;
}

__global__ __launch_bounds__(256) void convert_lstm_kernel(
    const float* __restrict__ src, int srcw, int dstoff) {
    size_t i = ((size_t)blockIdx.x * 256 + threadIdx.x) * 4;
    int r = (int)(i / srcw);
    int k = (int)(i % srcw);
    float4 w = *(const float4*)(src + i);
    size_t o = (size_t)r * KTOT + dstoff + k;
    __nv_bfloat16 h0 = __float2bfloat16(w.x);
    __nv_bfloat16 h1 = __float2bfloat16(w.y);
    __nv_bfloat16 h2 = __float2bfloat16(w.z);
    __nv_bfloat16 h3 = __float2bfloat16(w.w);
    __nv_bfloat162 a, b, c, d;
    a.x = h0; a.y = h1; b.x = h2; b.y = h3;
    c.x = __float2bfloat16(w.x - __bfloat162float(h0));
    c.y = __float2bfloat16(w.y - __bfloat162float(h1));
    d.x = __float2bfloat16(w.z - __bfloat162float(h2));
    d.y = __float2bfloat16(w.w - __bfloat162float(h3));
    *(__nv_bfloat162*)(g_wl_hi + o) = a;
    *(__nv_bfloat162*)(g_wl_hi + o + 2) = b;
    *(__nv_bfloat162*)(g_wl_lo + o) = c;
    *(__nv_bfloat162*)(g_wl_lo + o + 2) = d;
}

// ---------------- K0: h0/c0 from condition ----------------
__global__ __launch_bounds__(256) void init_kernel(
    const float* __restrict__ cond, const float* __restrict__ Wh,
    const float* __restrict__ bh,   const float* __restrict__ Wc,
    const float* __restrict__ bc) {
    int j = blockIdx.x * 8 + (threadIdx.x >> 5);
    int lane = threadIdx.x & 31;
    if (blockIdx.x < 8) {
        int idx = blockIdx.x * 256 + threadIdx.x;
        if (idx < TT * BB) g_best[idx] = 0ull;
    }
    const float* cr = cond + (size_t)lane * EE;
    const float* wh = Wh + (size_t)j * EE;
    const float* wc = Wc + (size_t)j * EE;
    float ah = bh[j], ac = bc[j];
#pragma unroll 4
    for (int k = 0; k < EE; k += 4) {
        float4 c4 = *(const float4*)(cr + k);
        float4 h4 = *(const float4*)(wh + k);
        float4 q4 = *(const float4*)(wc + k);
        ah = fmaf(c4.x, h4.x, ah); ah = fmaf(c4.y, h4.y, ah);
        ah = fmaf(c4.z, h4.z, ah); ah = fmaf(c4.w, h4.w, ah);
        ac = fmaf(c4.x, q4.x, ac); ac = fmaf(c4.y, q4.y, ac);
        ac = fmaf(c4.z, q4.z, ac); ac = fmaf(c4.w, q4.w, ac);
    }
    g_c[j * BB + lane] = ac;
    __nv_bfloat16 hi = __float2bfloat16(ah);
    g_xh_hi[lane * KTOT + EE + j] = hi;
    g_xh_lo[lane * KTOT + EE + j] = __float2bfloat16(ah - __bfloat162float(hi));
}

// ---------------- K-gather: embed(tok) -> xh bf16 hi/lo ----------------
__global__ __launch_bounds__(256) void gather_kernel(
    const float* __restrict__ embed, int t) {
    int idx = blockIdx.x * 256 + threadIdx.x;
    int b = idx & 31;
    int k = idx >> 5;
    int tok = START_TOK;
    if (t > 0) tok = decode_tok(g_best[(t - 1) * BB + b]);
    float val = embed[(size_t)tok * EE + k];
    __nv_bfloat16 hi = __float2bfloat16(val);
    g_xh_hi[b * KTOT + k] = hi;
    g_xh_lo[b * KTOT + k] = __float2bfloat16(val - __bfloat162float(hi));
}

// ---------------- K1a: lstm gate GEMM via mma.sync bf16 hi/lo --------------
__global__ __launch_bounds__(256) void lstm_mma_kernel() {
    extern __shared__ __align__(16) char dsm[];
    unsigned sb = (unsigned)__cvta_generic_to_shared(dsm);
    int tid = threadIdx.x;
    int l = tid & 31;
    int w = tid >> 5;
    int m0 = blockIdx.x * 128;
    int seg = blockIdx.y;
    int k0seg = seg * KSEG;

    auto stage_chunk = [&](int c) {
        int s = c & 3;
        int kc = k0seg + c * LKC;
        int srow = tid >> 1;
        int shalf = (tid & 1) * 32;
        const __nv_bfloat16* shi = g_wl_hi + (size_t)(m0 + srow) * KTOT + kc + (tid & 1) * 16;
        const __nv_bfloat16* slo = g_wl_lo + (size_t)(m0 + srow) * KTOT + kc + (tid & 1) * 16;
        unsigned dhi = sb + SM_WHI + s * 10240 + srow * 80 + shalf;
        unsigned dlo = sb + SM_WLO + s * 10240 + srow * 80 + shalf;
        cp_async16(dhi, shi);
        cp_async16(dhi + 16, shi + 8);
        cp_async16(dlo, slo);
        cp_async16(dlo + 16, slo + 8);
        if (tid < 128) {
            int hr = tid >> 2, hi_ = tid & 3;
            cp_async16(sb + SM_HHI + s * 2560 + hr * 80 + hi_ * 16,
                       g_xh_hi + (size_t)hr * KTOT + kc + hi_ * 8);
            cp_async16(sb + SM_HLO + s * 2560 + hr * 80 + hi_ * 16,
                       g_xh_lo + (size_t)hr * KTOT + kc + hi_ * 8);
        }
        cp_commit();
    };

    stage_chunk(0); stage_chunk(1); stage_chunk(2);

    float acc[4][4];
#pragma unroll
    for (int bt = 0; bt < 4; bt++)
#pragma unroll
        for (int i = 0; i < 4; i++) acc[bt][i] = 0.f;

    unsigned aoff = (unsigned)((w * 16 + (l & 15)) * 80 + (l >> 4) * 16);
    unsigned brow = (unsigned)(((l >> 4) * 8) + (l & 7));
    unsigned bkadd = (unsigned)(((l >> 3) & 1) * 16);
    unsigned boff0 = brow * 80 + bkadd;
    unsigned boff1 = (brow + 16) * 80 + bkadd;

    for (int cc = 0; cc < NCHUNK_L; cc++) {
        if (cc < NCHUNK_L - 2)
            asm volatile("cp.async.wait_group 2;" ::: "memory");
        else if (cc == NCHUNK_L - 2)
            asm volatile("cp.async.wait_group 1;" ::: "memory");
        else
            asm volatile("cp.async.wait_group 0;" ::: "memory");
        __syncthreads();
        int s = cc & 3;
        unsigned whib = sb + SM_WHI + s * 10240;
        unsigned wlob = sb + SM_WLO + s * 10240;
        unsigned hhib = sb + SM_HHI + s * 2560;
        unsigned hlob = sb + SM_HLO + s * 2560;
#pragma unroll
        for (int k16 = 0; k16 < 2; k16++) {
            unsigned kb = (unsigned)(k16 * 32);
            unsigned ahi[4], alo[4], bh0[4], bh1[4], bl0[4], bl1[4];
            ldsm_x4(whib + aoff + kb, ahi);
            ldsm_x4(wlob + aoff + kb, alo);
            ldsm_x4(hhib + boff0 + kb, bh0);
            ldsm_x4(hhib + boff1 + kb, bh1);
            ldsm_x4(hlob + boff0 + kb, bl0);
            ldsm_x4(hlob + boff1 + kb, bl1);
            MMA_BF16(acc[0], ahi, bh0 + 0);
            MMA_BF16(acc[0], ahi, bl0 + 0);
            MMA_BF16(acc[0], alo, bh0 + 0);
            MMA_BF16(acc[1], ahi, bh0 + 2);
            MMA_BF16(acc[1], ahi, bl0 + 2);
            MMA_BF16(acc[1], alo, bh0 + 2);
            MMA_BF16(acc[2], ahi, bh1 + 0);
            MMA_BF16(acc[2], ahi, bl1 + 0);
            MMA_BF16(acc[2], alo, bh1 + 0);
            MMA_BF16(acc[3], ahi, bh1 + 2);
            MMA_BF16(acc[3], ahi, bl1 + 2);
            MMA_BF16(acc[3], alo, bh1 + 2);
        }
        __syncthreads();
        if (cc + 3 < NCHUNK_L) stage_chunk(cc + 3);
    }

    float* part = g_gpart + (size_t)seg * MROWS * BB;
    int rlo = m0 + w * 16 + (l >> 2);
    int rhi = rlo + 8;
#pragma unroll
    for (int bt = 0; bt < 4; bt++) {
        int be = bt * 8 + (l & 3) * 2;
        int bo = be + 1;
        part[rlo * BB + be] = acc[bt][0];
        part[rlo * BB + bo] = acc[bt][1];
        part[rhi * BB + be] = acc[bt][2];
        part[rhi * BB + bo] = acc[bt][3];
    }
}

// ---------------- K1b: combine partials + cell + h bf16 split ---------------
__global__ __launch_bounds__(256) void cell_kernel(
    const float* __restrict__ bih, const float* __restrict__ bhh) {
    int idx = blockIdx.x * 256 + threadIdx.x;
    int b = idx & 31;
    int j = idx >> 5;
    float a[4] = {0.f, 0.f, 0.f, 0.f};
#pragma unroll
    for (int seg = 0; seg < SPLITK; seg++) {
        const float* part = g_gpart + (size_t)seg * MROWS * BB;
#pragma unroll
        for (int gate = 0; gate < 4; gate++)
            a[gate] += part[(size_t)(gate * HH + j) * BB + b];
    }
#pragma unroll
    for (int gate = 0; gate < 4; gate++) {
        int r = gate * HH + j;
        a[gate] += bih[r] + bhh[r];
    }
    float ig = 1.0f / (1.0f + expf(-a[0]));
    float fg = 1.0f / (1.0f + expf(-a[1]));
    float gg = tanhf(a[2]);
    float og = 1.0f / (1.0f + expf(-a[3]));
    float c = fg * g_c[j * BB + b] + ig * gg;
    float h = og * tanhf(c);
    g_c[j * BB + b] = c;
    __nv_bfloat16 hi = __float2bfloat16(h);
    g_xh_hi[b * KTOT + EE + j] = hi;
    g_xh_lo[b * KTOT + EE + j] = __float2bfloat16(h - __bfloat162float(hi));
}

// ---------------- K2: logits mma, TILEV=256, 2-stage --------------
// 8 warps; warp w owns v-rows [v0 + w*32, +32) as two m16 tiles (vt 0,1).
__global__ __launch_bounds__(256) void logits_kernel(
    const float* __restrict__ bout, float* __restrict__ stage,
    unsigned long long* __restrict__ best, int t, unsigned key0, unsigned key1) {
    extern __shared__ __align__(16) char dsm[];
    unsigned sb = (unsigned)__cvta_generic_to_shared(dsm);
    int tid = threadIdx.x;
    int l = tid & 31;
    int w = tid >> 5;
    int bid = blockIdx.x;
    if (t & 1) bid = NBLK_LOG - 1 - bid;
    int v0 = bid * L2_TILEV;

    auto stage_chunk = [&](int c) {
        int s = c & 1;
        int cc2 = (t & 1) ? (NCHUNK - 1 - c) : c;
        int kc = cc2 * LKC;
        const __nv_bfloat16* shi = g_whi + (size_t)(v0 + tid) * HH + kc;
        const __nv_bfloat16* slo = g_wlo + (size_t)(v0 + tid) * HH + kc;
        unsigned dhi = sb + S2_WHI + s * 20480 + tid * 80;
        unsigned dlo = sb + S2_WLO + s * 20480 + tid * 80;
#pragma unroll
        for (int i = 0; i < 4; i++) {
            cp_async16(dhi + i * 16, shi + i * 8);
            cp_async16(dlo + i * 16, slo + i * 8);
        }
        if (tid < 128) {
            int hr = tid >> 2, hi_ = tid & 3;
            cp_async16(sb + S2_HHI + s * 2560 + hr * 80 + hi_ * 16,
                       g_xh_hi + (size_t)hr * KTOT + EE + kc + hi_ * 8);
            cp_async16(sb + S2_HLO + s * 2560 + hr * 80 + hi_ * 16,
                       g_xh_lo + (size_t)hr * KTOT + EE + kc + hi_ * 8);
        }
        cp_commit();
    };

    stage_chunk(0); stage_chunk(1);

    float acc[2][4][4];
#pragma unroll
    for (int vt = 0; vt < 2; vt++)
#pragma unroll
        for (int bt = 0; bt < 4; bt++)
#pragma unroll
            for (int i = 0; i < 4; i++) acc[vt][bt][i] = 0.f;

    unsigned aoff0 = (unsigned)((w * 32 + (l & 15)) * 80 + (l >> 4) * 16);
    unsigned aoff1 = aoff0 + 16 * 80;
    unsigned brow = (unsigned)(((l >> 4) * 8) + (l & 7));
    unsigned bkadd = (unsigned)(((l >> 3) & 1) * 16);
    unsigned boff0 = brow * 80 + bkadd;
    unsigned boff1 = (brow + 16) * 80 + bkadd;

    for (int cc = 0; cc < NCHUNK; cc++) {
        if (cc == NCHUNK - 1)
            asm volatile("cp.async.wait_group 0;" ::: "memory");
        else
            asm volatile("cp.async.wait_group 1;" ::: "memory");
        __syncthreads();
        int s = cc & 1;
        unsigned whib = sb + S2_WHI + s * 20480;
        unsigned wlob = sb + S2_WLO + s * 20480;
        unsigned hhib = sb + S2_HHI + s * 2560;
        unsigned hlob = sb + S2_HLO + s * 2560;
#pragma unroll
        for (int k16 = 0; k16 < 2; k16++) {
            unsigned kb = (unsigned)(k16 * 32);
            unsigned bh0[4], bh1[4], bl0[4], bl1[4];
            ldsm_x4(hhib + boff0 + kb, bh0);
            ldsm_x4(hhib + boff1 + kb, bh1);
            ldsm_x4(hlob + boff0 + kb, bl0);
            ldsm_x4(hlob + boff1 + kb, bl1);
#pragma unroll
            for (int vt = 0; vt < 2; vt++) {
                unsigned ahi[4], alo[4];
                ldsm_x4(whib + (vt ? aoff1 : aoff0) + kb, ahi);
                ldsm_x4(wlob + (vt ? aoff1 : aoff0) + kb, alo);
                MMA_BF16(acc[vt][0], ahi, bh0 + 0);
                MMA_BF16(acc[vt][0], ahi, bl0 + 0);
                MMA_BF16(acc[vt][0], alo, bh0 + 0);
                MMA_BF16(acc[vt][1], ahi, bh0 + 2);
                MMA_BF16(acc[vt][1], ahi, bl0 + 2);
                MMA_BF16(acc[vt][1], alo, bh0 + 2);
                MMA_BF16(acc[vt][2], ahi, bh1 + 0);
                MMA_BF16(acc[vt][2], ahi, bl1 + 0);
                MMA_BF16(acc[vt][2], alo, bh1 + 0);
                MMA_BF16(acc[vt][3], ahi, bh1 + 2);
                MMA_BF16(acc[vt][3], ahi, bl1 + 2);
                MMA_BF16(acc[vt][3], alo, bh1 + 2);
            }
        }
        __syncthreads();
        if (cc + 2 < NCHUNK) stage_chunk(cc + 2);
    }

    auto gkey = [&](float logit, int b, int v) -> unsigned long long {
        unsigned o0, o1;
        threefry2x32_dev(key0, key1, 0u, (unsigned)(b * VV + v), o0, o1);
        unsigned bits = o0 ^ o1;
        float u = __uint_as_float(0x3f800000u | (bits >> 9)) - 1.0f;
        u = fmaxf(u + F32_TINY, F32_TINY);
        float g = -logf(-logf(u));
        float val = logit + g;
        return ((unsigned long long)ford(val) << 32) |
               (unsigned long long)(0xFFFFFFFFu - (unsigned)v);
    };

    unsigned long long bk[8];
#pragma unroll
    for (int i = 0; i < 8; i++) bk[i] = 0ull;

#pragma unroll
    for (int vt = 0; vt < 2; vt++) {
        int vlo = v0 + w * 32 + vt * 16 + (l >> 2);
        int vhi = vlo + 8;
        float bolo = bout[vlo];
        float bohi = bout[vhi];
#pragma unroll
        for (int bt = 0; bt < 4; bt++) {
            int be = bt * 8 + (l & 3) * 2;
            int bo = be + 1;
            float x0 = acc[vt][bt][0] + bolo;
            float x1 = acc[vt][bt][1] + bolo;
            float x2 = acc[vt][bt][2] + bohi;
            float x3 = acc[vt][bt][3] + bohi;
            stcs(&stage[((size_t)be * TT + t) * VV + vlo], x0);
            stcs(&stage[((size_t)bo * TT + t) * VV + vlo], x1);
            stcs(&stage[((size_t)be * TT + t) * VV + vhi], x2);
            stcs(&stage[((size_t)bo * TT + t) * VV + vhi], x3);
            bk[bt * 2]     = u64max(bk[bt * 2],     u64max(gkey(x0, be, vlo), gkey(x2, be, vhi)));
            bk[bt * 2 + 1] = u64max(bk[bt * 2 + 1], u64max(gkey(x1, bo, vlo), gkey(x3, bo, vhi)));
        }
    }
#pragma unroll
    for (int off = 4; off < 32; off <<= 1)
#pragma unroll
        for (int i = 0; i < 8; i++)
            bk[i] = u64max(bk[i], __shfl_xor_sync(0xffffffffu, bk[i], off));

    unsigned long long* parts = (unsigned long long*)(dsm + S2_PARTS);
    if (l < 4) {
#pragma unroll
        for (int bt = 0; bt < 4; bt++) {
            parts[w * 32 + bt * 8 + l * 2]     = bk[bt * 2];
            parts[w * 32 + bt * 8 + l * 2 + 1] = bk[bt * 2 + 1];
        }
    }
    __syncthreads();
    if (tid < 32) {
        unsigned long long m = 0ull;
#pragma unroll
        for (int wi = 0; wi < 8; wi++) m = u64max(m, parts[wi * 32 + tid]);
        atomicMax(&best[t * BB + tid], m);
    }
}

// ---------------- final: captions ----------------
__global__ void caption_kernel(float* __restrict__ cap_f, int* __restrict__ cap_i) {
    int idx = blockIdx.x * 256 + threadIdx.x;
    int tt = idx & 63;
    int b = idx >> 6;
    int v = decode_tok(g_best[tt * BB + b]);
    if (cap_f) cap_f[b * TT + tt] = (float)v;
    if (cap_i) cap_i[b * TT + tt] = v;
}

// ---------------- final: transpose [b][t][v] -> [b][v][t] ----------------
__global__ __launch_bounds__(256) void transpose_kernel(
    const float* __restrict__ stage, float* __restrict__ out) {
    __shared__ float tile[128][65];
    int b = blockIdx.x / 250;
    int vc = blockIdx.x % 250;
    int v0 = vc * 128;
    const float* src = stage + (size_t)b * TT * VV + v0;
#pragma unroll
    for (int l = 0; l < 32; l++) {
        int e = threadIdx.x + l * 256;
        int tt = e >> 7;
        int vi = e & 127;
        tile[vi][tt] = src[(size_t)tt * VV + vi];
    }
    __syncthreads();
    float* dst = out + ((size_t)b * VV + v0) * TT;
#pragma unroll
    for (int l = 0; l < 32; l++) {
        int e = threadIdx.x + l * 256;
        int vi = e >> 6;
        int tt = e & 63;
        dst[(size_t)vi * TT + tt] = tile[vi][tt];
    }
}

// ---------------- host threefry ----------------
static void host_threefry(unsigned k0, unsigned k1, unsigned x0, unsigned x1,
                          unsigned& o0, unsigned& o1) {
    unsigned ks2 = k0 ^ k1 ^ 0x1BD11BDAu;
    x0 += k0; x1 += k1;
#define HTF_RND(r) { x0 += x1; x1 = (x1 << r) | (x1 >> (32 - r)); x1 ^= x0; }
    HTF_RND(13) HTF_RND(15) HTF_RND(26) HTF_RND(6)  x0 += k1;  x1 += ks2 + 1u;
    HTF_RND(17) HTF_RND(29) HTF_RND(16) HTF_RND(24) x0 += ks2; x1 += k0 + 2u;
    HTF_RND(13) HTF_RND(15) HTF_RND(26) HTF_RND(6)  x0 += k0;  x1 += k1 + 3u;
    HTF_RND(17) HTF_RND(29) HTF_RND(16) HTF_RND(24) x0 += k1;  x1 += ks2 + 4u;
    HTF_RND(13) HTF_RND(15) HTF_RND(26) HTF_RND(6)  x0 += ks2; x1 += k0 + 5u;
#undef HTF_RND
    o0 = x0; o1 = x1;
}

extern "C" void kernel_launch(void* const* d_in, const int* in_sizes, int n_in,
                              void* d_out, int out_size) {
    const float* condition = (const float*)d_in[0];
    const float* Wh    = (const float*)d_in[1];
    const float* bh    = (const float*)d_in[2];
    const float* Wc    = (const float*)d_in[3];
    const float* bc    = (const float*)d_in[4];
    const float* embed = (const float*)d_in[5];
    const float* Wih   = (const float*)d_in[6];
    const float* bih   = (const float*)d_in[7];
    const float* Whh   = (const float*)d_in[8];
    const float* bhh   = (const float*)d_in[9];
    const float* Wout  = (const float*)d_in[10];
    const float* bout  = (const float*)d_in[11];

    float* stage;
    unsigned long long* best;
    cudaGetSymbolAddress((void**)&stage, g_stage);
    cudaGetSymbolAddress((void**)&best, g_best);

    const long long n_cap = (long long)BB * TT;
    const long long n_log = (long long)BB * VV * TT;
    float* cap_f = nullptr;
    int*   cap_i = nullptr;
    float* log_out = nullptr;
    long long osz = (long long)out_size;
    if (osz == n_cap + n_log) {
        cap_f = (float*)d_out;
        log_out = (float*)d_out + n_cap;
    } else if (osz == n_log) {
        log_out = (float*)d_out;
    } else if (osz == n_cap) {
        cap_i = (int*)d_out;
    } else {
        cap_f = (float*)d_out;
        log_out = (float*)d_out + n_cap;
    }

    cudaFuncSetAttribute(logits_kernel,
                         cudaFuncAttributeMaxDynamicSharedMemorySize, SMEM_LOG);
    cudaFuncSetAttribute(lstm_mma_kernel,
                         cudaFuncAttributeMaxDynamicSharedMemorySize, SMEM_MMA);

    convert_kernel<<<VV * HH / 1024, 256>>>(Wout);
    convert_lstm_kernel<<<MROWS * EE / 1024, 256>>>(Wih, EE, 0);
    convert_lstm_kernel<<<MROWS * HH / 1024, 256>>>(Whh, HH, EE);
    init_kernel<<<128, 256>>>(condition, Wh, bh, Wc, bc);

    for (int t = 0; t < TT; t++) {
        gather_kernel<<<64, 256>>>(embed, t);
        dim3 ggrid(MROWS / 128, SPLITK);
        lstm_mma_kernel<<<ggrid, 256, SMEM_MMA>>>();
        cell_kernel<<<128, 256>>>(bih, bhh);
        unsigned o0, o1;
        host_threefry(0u, 42u, 0u, (unsigned)t, o0, o1);
        logits_kernel<<<NBLK_LOG, 256, SMEM_LOG>>>(bout, stage, best, t, o0, o1);
    }
    caption_kernel<<<8, 256>>>(cap_f, cap_i);
    if (log_out) transpose_kernel<<<8000, 256>>>(stage, log_out);
}

// round 17
// speedup vs baseline: 1.2750x; 1.2750x over previous
#include <cuda_runtime.h>
#include <cuda_bf16.h>
#include <math.h>

#define BB 32
#define EE 512
#define HH 1024
#define VV 32000
#define TT 64
#define START_TOK 1
#define F32_TINY 1.17549435e-38f
#define KTOT 1536
#define SPLITK 8
#define KSEG (KTOT / SPLITK)     // 192
#define LKC 32
#define NCHUNK_L (KSEG / LKC)    // 6
#define NCHUNK (HH / LKC)        // 32
#define NBLK_LOG 250
#define MROWS 4096
// shared smem map for both mma kernels (4-stage, 128 rows)
#define SM_WHI 0
#define SM_WLO 40960
#define SM_HHI 81920
#define SM_HLO 92160
#define SM_PARTS 102400
#define SMEM_MMA 104448

// ---------------- device scratch ----------------
__device__ __align__(16) float g_c[HH * BB];
__device__ __align__(16) float g_gpart[SPLITK * MROWS * BB];
__device__ unsigned long long g_best[TT * BB];
__device__ __align__(16) float g_stage[(size_t)BB * TT * VV]; // [b][t][v]
__device__ __align__(16) __nv_bfloat16 g_whi[(size_t)VV * HH];
__device__ __align__(16) __nv_bfloat16 g_wlo[(size_t)VV * HH];
__device__ __align__(16) __nv_bfloat16 g_wl_hi[(size_t)MROWS * KTOT];
__device__ __align__(16) __nv_bfloat16 g_wl_lo[(size_t)MROWS * KTOT];
__device__ __align__(16) __nv_bfloat16 g_xh_hi[BB * KTOT];
__device__ __align__(16) __nv_bfloat16 g_xh_lo[BB * KTOT];

// ---------------- threefry2x32 (JAX-compatible) ----------------
__device__ __forceinline__ void threefry2x32_dev(unsigned k0, unsigned k1,
                                                 unsigned x0, unsigned x1,
                                                 unsigned& o0, unsigned& o1) {
    unsigned ks2 = k0 ^ k1 ^ 0x1BD11BDAu;
    x0 += k0; x1 += k1;
#define TF_RND(r) { x0 += x1; x1 = __funnelshift_l(x1, x1, r); x1 ^= x0; }
    TF_RND(13) TF_RND(15) TF_RND(26) TF_RND(6)  x0 += k1;  x1 += ks2 + 1u;
    TF_RND(17) TF_RND(29) TF_RND(16) TF_RND(24) x0 += ks2; x1 += k0 + 2u;
    TF_RND(13) TF_RND(15) TF_RND(26) TF_RND(6)  x0 += k0;  x1 += k1 + 3u;
    TF_RND(17) TF_RND(29) TF_RND(16) TF_RND(24) x0 += k1;  x1 += ks2 + 4u;
    TF_RND(13) TF_RND(15) TF_RND(26) TF_RND(6)  x0 += ks2; x1 += k0 + 5u;
#undef TF_RND
    o0 = x0; o1 = x1;
}

__device__ __forceinline__ unsigned ford(float f) {
    unsigned u = __float_as_uint(f);
    return (u & 0x80000000u) ? ~u : (u | 0x80000000u);
}
__device__ __forceinline__ unsigned long long u64max(unsigned long long a,
                                                     unsigned long long b) {
    return a > b ? a : b;
}
__device__ __forceinline__ int decode_tok(unsigned long long key) {
    return (int)(0xFFFFFFFFu - (unsigned)(key & 0xFFFFFFFFull));
}

// ---------------- cp.async / ldsm / streaming-store helpers ----------------
__device__ __forceinline__ void cp_async16(unsigned dst, const void* src) {
    asm volatile("cp.async.cg.shared.global [%0], [%1], 16;"
                 :: "r"(dst), "l"(src) : "memory");
}
__device__ __forceinline__ void cp_commit() {
    asm volatile("cp.async.commit_group;" ::: "memory");
}
__device__ __forceinline__ void ldsm_x4(unsigned addr, unsigned* r) {
    asm volatile("ldmatrix.sync.aligned.m8n8.x4.shared.b16 {%0,%1,%2,%3}, [%4];"
                 : "=r"(r[0]), "=r"(r[1]), "=r"(r[2]), "=r"(r[3]) : "r"(addr));
}
__device__ __forceinline__ void stcs(float* p, float v) {
    asm volatile("st.global.cs.f32 [%0], %1;" :: "l"(p), "f"(v) : "memory");
}
#define MMA_BF16(c, a, b) \
    asm volatile("mma.sync.aligned.m16n8k16.row.col.f32.bf16.bf16.f32 " \
        "{%0,%1,%2,%3}, {%4,%5,%6,%7}, {%8,%9}, {%0,%1,%2,%3};" \
        : "+f"((c)[0]), "+f"((c)[1]), "+f"((c)[2]), "+f"((c)[3]) \
        : "r"((a)[0]), "r"((a)[1]), "r"((a)[2]), "r"((a)[3]), \
          "r"((b)[0]), "r"((b)[1]))

// ---------------- converts ----------------
__global__ __launch_bounds__(256) void convert_kernel(const float* __restrict__ W) {
    size_t i = ((size_t)blockIdx.x * 256 + threadIdx.x) * 4;
    float4 w = *(const float4*)(W + i);
    __nv_bfloat16 h0 = __float2bfloat16(w.x);
    __nv_bfloat16 h1 = __float2bfloat16(w.y);
    __nv_bfloat16 h2 = __float2bfloat16(w.z);
    __nv_bfloat16 h3 = __float2bfloat16(w.w);
    __nv_bfloat162 a, b, c, d;
    a.x = h0; a.y = h1; b.x = h2; b.y = h3;
    c.x = __float2bfloat16(w.x - __bfloat162float(h0));
    c.y = __float2bfloat16(w.y - __bfloat162float(h1));
    d.x = __float2bfloat16(w.z - __bfloat162float(h2));
    d.y = __float2bfloat16(w.w - __bfloat162float(h3));
    *(__nv_bfloat162*)(g_whi + i) = a;
    *(__nv_bfloat162*)(g_whi + i + 2) = b;
    *(__nv_bfloat162*)(g_wlo + i) = c;
    *(__nv_bfloat162*)(g_wlo + i + 2) = d;
}

__global__ __launch_bounds__(256) void convert_lstm_kernel(
    const float* __restrict__ src, int srcw, int dstoff) {
    size_t i = ((size_t)blockIdx.x * 256 + threadIdx.x) * 4;
    int r = (int)(i / srcw);
    int k = (int)(i % srcw);
    float4 w = *(const float4*)(src + i);
    size_t o = (size_t)r * KTOT + dstoff + k;
    __nv_bfloat16 h0 = __float2bfloat16(w.x);
    __nv_bfloat16 h1 = __float2bfloat16(w.y);
    __nv_bfloat16 h2 = __float2bfloat16(w.z);
    __nv_bfloat16 h3 = __float2bfloat16(w.w);
    __nv_bfloat162 a, b, c, d;
    a.x = h0; a.y = h1; b.x = h2; b.y = h3;
    c.x = __float2bfloat16(w.x - __bfloat162float(h0));
    c.y = __float2bfloat16(w.y - __bfloat162float(h1));
    d.x = __float2bfloat16(w.z - __bfloat162float(h2));
    d.y = __float2bfloat16(w.w - __bfloat162float(h3));
    *(__nv_bfloat162*)(g_wl_hi + o) = a;
    *(__nv_bfloat162*)(g_wl_hi + o + 2) = b;
    *(__nv_bfloat162*)(g_wl_lo + o) = c;
    *(__nv_bfloat162*)(g_wl_lo + o + 2) = d;
}

// ---------------- K0: h0/c0 from condition ----------------
__global__ __launch_bounds__(256) void init_kernel(
    const float* __restrict__ cond, const float* __restrict__ Wh,
    const float* __restrict__ bh,   const float* __restrict__ Wc,
    const float* __restrict__ bc) {
    int j = blockIdx.x * 8 + (threadIdx.x >> 5);
    int lane = threadIdx.x & 31;
    if (blockIdx.x < 8) {
        int idx = blockIdx.x * 256 + threadIdx.x;
        if (idx < TT * BB) g_best[idx] = 0ull;
    }
    const float* cr = cond + (size_t)lane * EE;
    const float* wh = Wh + (size_t)j * EE;
    const float* wc = Wc + (size_t)j * EE;
    float ah = bh[j], ac = bc[j];
#pragma unroll 4
    for (int k = 0; k < EE; k += 4) {
        float4 c4 = *(const float4*)(cr + k);
        float4 h4 = *(const float4*)(wh + k);
        float4 q4 = *(const float4*)(wc + k);
        ah = fmaf(c4.x, h4.x, ah); ah = fmaf(c4.y, h4.y, ah);
        ah = fmaf(c4.z, h4.z, ah); ah = fmaf(c4.w, h4.w, ah);
        ac = fmaf(c4.x, q4.x, ac); ac = fmaf(c4.y, q4.y, ac);
        ac = fmaf(c4.z, q4.z, ac); ac = fmaf(c4.w, q4.w, ac);
    }
    g_c[j * BB + lane] = ac;
    __nv_bfloat16 hi = __float2bfloat16(ah);
    g_xh_hi[lane * KTOT + EE + j] = hi;
    g_xh_lo[lane * KTOT + EE + j] = __float2bfloat16(ah - __bfloat162float(hi));
}

// ---------------- K-gather: embed(tok) -> xh bf16 hi/lo ----------------
__global__ __launch_bounds__(256) void gather_kernel(
    const float* __restrict__ embed, int t) {
    int idx = blockIdx.x * 256 + threadIdx.x;
    int b = idx & 31;
    int k = idx >> 5;
    int tok = START_TOK;
    if (t > 0) tok = decode_tok(g_best[(t - 1) * BB + b]);
    float val = embed[(size_t)tok * EE + k];
    __nv_bfloat16 hi = __float2bfloat16(val);
    g_xh_hi[b * KTOT + k] = hi;
    g_xh_lo[b * KTOT + k] = __float2bfloat16(val - __bfloat162float(hi));
}

// ---------------- K1a: lstm gate GEMM via mma.sync bf16 hi/lo --------------
__global__ __launch_bounds__(256) void lstm_mma_kernel() {
    extern __shared__ __align__(16) char dsm[];
    unsigned sb = (unsigned)__cvta_generic_to_shared(dsm);
    int tid = threadIdx.x;
    int l = tid & 31;
    int w = tid >> 5;
    int m0 = blockIdx.x * 128;
    int seg = blockIdx.y;
    int k0seg = seg * KSEG;

    auto stage_chunk = [&](int c) {
        int s = c & 3;
        int kc = k0seg + c * LKC;
        int srow = tid >> 1;
        int shalf = (tid & 1) * 32;
        const __nv_bfloat16* shi = g_wl_hi + (size_t)(m0 + srow) * KTOT + kc + (tid & 1) * 16;
        const __nv_bfloat16* slo = g_wl_lo + (size_t)(m0 + srow) * KTOT + kc + (tid & 1) * 16;
        unsigned dhi = sb + SM_WHI + s * 10240 + srow * 80 + shalf;
        unsigned dlo = sb + SM_WLO + s * 10240 + srow * 80 + shalf;
        cp_async16(dhi, shi);
        cp_async16(dhi + 16, shi + 8);
        cp_async16(dlo, slo);
        cp_async16(dlo + 16, slo + 8);
        if (tid < 128) {
            int hr = tid >> 2, hi_ = tid & 3;
            cp_async16(sb + SM_HHI + s * 2560 + hr * 80 + hi_ * 16,
                       g_xh_hi + (size_t)hr * KTOT + kc + hi_ * 8);
            cp_async16(sb + SM_HLO + s * 2560 + hr * 80 + hi_ * 16,
                       g_xh_lo + (size_t)hr * KTOT + kc + hi_ * 8);
        }
        cp_commit();
    };

    stage_chunk(0); stage_chunk(1); stage_chunk(2);

    float acc[4][4];
#pragma unroll
    for (int bt = 0; bt < 4; bt++)
#pragma unroll
        for (int i = 0; i < 4; i++) acc[bt][i] = 0.f;

    unsigned aoff = (unsigned)((w * 16 + (l & 15)) * 80 + (l >> 4) * 16);
    unsigned brow = (unsigned)(((l >> 4) * 8) + (l & 7));
    unsigned bkadd = (unsigned)(((l >> 3) & 1) * 16);
    unsigned boff0 = brow * 80 + bkadd;
    unsigned boff1 = (brow + 16) * 80 + bkadd;

    for (int cc = 0; cc < NCHUNK_L; cc++) {
        if (cc < NCHUNK_L - 2)
            asm volatile("cp.async.wait_group 2;" ::: "memory");
        else if (cc == NCHUNK_L - 2)
            asm volatile("cp.async.wait_group 1;" ::: "memory");
        else
            asm volatile("cp.async.wait_group 0;" ::: "memory");
        __syncthreads();
        int s = cc & 3;
        unsigned whib = sb + SM_WHI + s * 10240;
        unsigned wlob = sb + SM_WLO + s * 10240;
        unsigned hhib = sb + SM_HHI + s * 2560;
        unsigned hlob = sb + SM_HLO + s * 2560;
#pragma unroll
        for (int k16 = 0; k16 < 2; k16++) {
            unsigned kb = (unsigned)(k16 * 32);
            unsigned ahi[4], alo[4], bh0[4], bh1[4], bl0[4], bl1[4];
            ldsm_x4(whib + aoff + kb, ahi);
            ldsm_x4(wlob + aoff + kb, alo);
            ldsm_x4(hhib + boff0 + kb, bh0);
            ldsm_x4(hhib + boff1 + kb, bh1);
            ldsm_x4(hlob + boff0 + kb, bl0);
            ldsm_x4(hlob + boff1 + kb, bl1);
            MMA_BF16(acc[0], ahi, bh0 + 0);
            MMA_BF16(acc[0], ahi, bl0 + 0);
            MMA_BF16(acc[0], alo, bh0 + 0);
            MMA_BF16(acc[1], ahi, bh0 + 2);
            MMA_BF16(acc[1], ahi, bl0 + 2);
            MMA_BF16(acc[1], alo, bh0 + 2);
            MMA_BF16(acc[2], ahi, bh1 + 0);
            MMA_BF16(acc[2], ahi, bl1 + 0);
            MMA_BF16(acc[2], alo, bh1 + 0);
            MMA_BF16(acc[3], ahi, bh1 + 2);
            MMA_BF16(acc[3], ahi, bl1 + 2);
            MMA_BF16(acc[3], alo, bh1 + 2);
        }
        __syncthreads();
        if (cc + 3 < NCHUNK_L) stage_chunk(cc + 3);
    }

    float* part = g_gpart + (size_t)seg * MROWS * BB;
    int rlo = m0 + w * 16 + (l >> 2);
    int rhi = rlo + 8;
#pragma unroll
    for (int bt = 0; bt < 4; bt++) {
        int be = bt * 8 + (l & 3) * 2;
        int bo = be + 1;
        part[rlo * BB + be] = acc[bt][0];
        part[rlo * BB + bo] = acc[bt][1];
        part[rhi * BB + be] = acc[bt][2];
        part[rhi * BB + bo] = acc[bt][3];
    }
}

// ---------------- K1b: combine partials + cell (float4 over b) -------------
// 64 blocks x 128 thr: thread owns (j, 4 consecutive b).
__global__ __launch_bounds__(128) void cell_kernel(
    const float* __restrict__ bih, const float* __restrict__ bhh) {
    int idx = blockIdx.x * 128 + threadIdx.x;   // 0..8191
    int bq = idx & 7;                            // b-quad
    int j = idx >> 3;
    int b0 = bq * 4;
    float4 a[4];
#pragma unroll
    for (int g = 0; g < 4; g++) a[g] = make_float4(0.f, 0.f, 0.f, 0.f);
#pragma unroll
    for (int seg = 0; seg < SPLITK; seg++) {
        const float* part = g_gpart + (size_t)seg * MROWS * BB;
#pragma unroll
        for (int g = 0; g < 4; g++) {
            float4 p = *(const float4*)&part[(size_t)(g * HH + j) * BB + b0];
            a[g].x += p.x; a[g].y += p.y; a[g].z += p.z; a[g].w += p.w;
        }
    }
    float bias[4];
#pragma unroll
    for (int g = 0; g < 4; g++) {
        int r = g * HH + j;
        bias[g] = bih[r] + bhh[r];
    }
    float4 cold = *(const float4*)&g_c[j * BB + b0];
    float cv[4] = {cold.x, cold.y, cold.z, cold.w};
    float4 cnew;
    float* cn = (float*)&cnew;
#pragma unroll
    for (int bi = 0; bi < 4; bi++) {
        float ai = ((float*)&a[0])[bi] + bias[0];
        float af = ((float*)&a[1])[bi] + bias[1];
        float ag = ((float*)&a[2])[bi] + bias[2];
        float ao = ((float*)&a[3])[bi] + bias[3];
        float ig = 1.0f / (1.0f + expf(-ai));
        float fg = 1.0f / (1.0f + expf(-af));
        float gg = tanhf(ag);
        float og = 1.0f / (1.0f + expf(-ao));
        float c = fg * cv[bi] + ig * gg;
        float h = og * tanhf(c);
        cn[bi] = c;
        __nv_bfloat16 hi = __float2bfloat16(h);
        g_xh_hi[(b0 + bi) * KTOT + EE + j] = hi;
        g_xh_lo[(b0 + bi) * KTOT + EE + j] =
            __float2bfloat16(h - __bfloat162float(hi));
    }
    *(float4*)&g_c[j * BB + b0] = cnew;
}

// ---------------- K2: logits mma (R15 config: TILEV=128, 4-stage) ----------
__global__ __launch_bounds__(256) void logits_kernel(
    const float* __restrict__ bout, float* __restrict__ stage,
    unsigned long long* __restrict__ best, int t, unsigned key0, unsigned key1) {
    extern __shared__ __align__(16) char dsm[];
    unsigned sb = (unsigned)__cvta_generic_to_shared(dsm);
    int tid = threadIdx.x;
    int l = tid & 31;
    int w = tid >> 5;
    int bid = blockIdx.x;
    if (t & 1) bid = NBLK_LOG - 1 - bid;
    int v0 = bid * 128;

    auto stage_chunk = [&](int c) {
        int s = c & 3;
        int cc2 = (t & 1) ? (NCHUNK - 1 - c) : c;
        int kc = cc2 * LKC;
        int srow = tid >> 1;
        int shalf = (tid & 1) * 32;
        const __nv_bfloat16* shi = g_whi + (size_t)(v0 + srow) * HH + kc + (tid & 1) * 16;
        const __nv_bfloat16* slo = g_wlo + (size_t)(v0 + srow) * HH + kc + (tid & 1) * 16;
        unsigned dhi = sb + SM_WHI + s * 10240 + srow * 80 + shalf;
        unsigned dlo = sb + SM_WLO + s * 10240 + srow * 80 + shalf;
        cp_async16(dhi, shi);
        cp_async16(dhi + 16, shi + 8);
        cp_async16(dlo, slo);
        cp_async16(dlo + 16, slo + 8);
        if (tid < 128) {
            int hr = tid >> 2, hi_ = tid & 3;
            cp_async16(sb + SM_HHI + s * 2560 + hr * 80 + hi_ * 16,
                       g_xh_hi + (size_t)hr * KTOT + EE + kc + hi_ * 8);
            cp_async16(sb + SM_HLO + s * 2560 + hr * 80 + hi_ * 16,
                       g_xh_lo + (size_t)hr * KTOT + EE + kc + hi_ * 8);
        }
        cp_commit();
    };

    stage_chunk(0); stage_chunk(1); stage_chunk(2);

    float acc[4][4];
#pragma unroll
    for (int bt = 0; bt < 4; bt++)
#pragma unroll
        for (int i = 0; i < 4; i++) acc[bt][i] = 0.f;

    unsigned aoff = (unsigned)((w * 16 + (l & 15)) * 80 + (l >> 4) * 16);
    unsigned brow = (unsigned)(((l >> 4) * 8) + (l & 7));
    unsigned bkadd = (unsigned)(((l >> 3) & 1) * 16);
    unsigned boff0 = brow * 80 + bkadd;
    unsigned boff1 = (brow + 16) * 80 + bkadd;

    for (int cc = 0; cc < NCHUNK; cc++) {
        if (cc < NCHUNK - 2)
            asm volatile("cp.async.wait_group 2;" ::: "memory");
        else if (cc == NCHUNK - 2)
            asm volatile("cp.async.wait_group 1;" ::: "memory");
        else
            asm volatile("cp.async.wait_group 0;" ::: "memory");
        __syncthreads();
        int s = cc & 3;
        unsigned whib = sb + SM_WHI + s * 10240;
        unsigned wlob = sb + SM_WLO + s * 10240;
        unsigned hhib = sb + SM_HHI + s * 2560;
        unsigned hlob = sb + SM_HLO + s * 2560;
#pragma unroll
        for (int k16 = 0; k16 < 2; k16++) {
            unsigned kb = (unsigned)(k16 * 32);
            unsigned ahi[4], alo[4], bh0[4], bh1[4], bl0[4], bl1[4];
            ldsm_x4(whib + aoff + kb, ahi);
            ldsm_x4(wlob + aoff + kb, alo);
            ldsm_x4(hhib + boff0 + kb, bh0);
            ldsm_x4(hhib + boff1 + kb, bh1);
            ldsm_x4(hlob + boff0 + kb, bl0);
            ldsm_x4(hlob + boff1 + kb, bl1);
            MMA_BF16(acc[0], ahi, bh0 + 0);
            MMA_BF16(acc[0], ahi, bl0 + 0);
            MMA_BF16(acc[0], alo, bh0 + 0);
            MMA_BF16(acc[1], ahi, bh0 + 2);
            MMA_BF16(acc[1], ahi, bl0 + 2);
            MMA_BF16(acc[1], alo, bh0 + 2);
            MMA_BF16(acc[2], ahi, bh1 + 0);
            MMA_BF16(acc[2], ahi, bl1 + 0);
            MMA_BF16(acc[2], alo, bh1 + 0);
            MMA_BF16(acc[3], ahi, bh1 + 2);
            MMA_BF16(acc[3], ahi, bl1 + 2);
            MMA_BF16(acc[3], alo, bh1 + 2);
        }
        __syncthreads();
        if (cc + 3 < NCHUNK) stage_chunk(cc + 3);
    }

    auto gkey = [&](float logit, int b, int v) -> unsigned long long {
        unsigned o0, o1;
        threefry2x32_dev(key0, key1, 0u, (unsigned)(b * VV + v), o0, o1);
        unsigned bits = o0 ^ o1;
        float u = __uint_as_float(0x3f800000u | (bits >> 9)) - 1.0f;
        u = fmaxf(u + F32_TINY, F32_TINY);
        float g = -logf(-logf(u));
        float val = logit + g;
        return ((unsigned long long)ford(val) << 32) |
               (unsigned long long)(0xFFFFFFFFu - (unsigned)v);
    };

    unsigned long long bk[8];
#pragma unroll
    for (int i = 0; i < 8; i++) bk[i] = 0ull;

    {
        int vlo = v0 + w * 16 + (l >> 2);
        int vhi = vlo + 8;
        float bolo = bout[vlo];
        float bohi = bout[vhi];
#pragma unroll
        for (int bt = 0; bt < 4; bt++) {
            int be = bt * 8 + (l & 3) * 2;
            int bo = be + 1;
            float x0 = acc[bt][0] + bolo;
            float x1 = acc[bt][1] + bolo;
            float x2 = acc[bt][2] + bohi;
            float x3 = acc[bt][3] + bohi;
            stcs(&stage[((size_t)be * TT + t) * VV + vlo], x0);
            stcs(&stage[((size_t)bo * TT + t) * VV + vlo], x1);
            stcs(&stage[((size_t)be * TT + t) * VV + vhi], x2);
            stcs(&stage[((size_t)bo * TT + t) * VV + vhi], x3);
            bk[bt * 2]     = u64max(bk[bt * 2],     u64max(gkey(x0, be, vlo), gkey(x2, be, vhi)));
            bk[bt * 2 + 1] = u64max(bk[bt * 2 + 1], u64max(gkey(x1, bo, vlo), gkey(x3, bo, vhi)));
        }
    }
#pragma unroll
    for (int off = 4; off < 32; off <<= 1)
#pragma unroll
        for (int i = 0; i < 8; i++)
            bk[i] = u64max(bk[i], __shfl_xor_sync(0xffffffffu, bk[i], off));

    unsigned long long* parts = (unsigned long long*)(dsm + SM_PARTS);
    if (l < 4) {
#pragma unroll
        for (int bt = 0; bt < 4; bt++) {
            parts[w * 32 + bt * 8 + l * 2]     = bk[bt * 2];
            parts[w * 32 + bt * 8 + l * 2 + 1] = bk[bt * 2 + 1];
        }
    }
    __syncthreads();
    if (tid < 32) {
        unsigned long long m = 0ull;
#pragma unroll
        for (int wi = 0; wi < 8; wi++) m = u64max(m, parts[wi * 32 + tid]);
        atomicMax(&best[t * BB + tid], m);
    }
}

// ---------------- final: captions ----------------
__global__ void caption_kernel(float* __restrict__ cap_f, int* __restrict__ cap_i) {
    int idx = blockIdx.x * 256 + threadIdx.x;
    int tt = idx & 63;
    int b = idx >> 6;
    int v = decode_tok(g_best[tt * BB + b]);
    if (cap_f) cap_f[b * TT + tt] = (float)v;
    if (cap_i) cap_i[b * TT + tt] = v;
}

// ---------------- final: transpose [b][t][v] -> [b][v][t] ----------------
__global__ __launch_bounds__(256) void transpose_kernel(
    const float* __restrict__ stage, float* __restrict__ out) {
    __shared__ float tile[128][65];
    int b = blockIdx.x / 250;
    int vc = blockIdx.x % 250;
    int v0 = vc * 128;
    const float* src = stage + (size_t)b * TT * VV + v0;
#pragma unroll
    for (int l = 0; l < 32; l++) {
        int e = threadIdx.x + l * 256;
        int tt = e >> 7;
        int vi = e & 127;
        tile[vi][tt] = src[(size_t)tt * VV + vi];
    }
    __syncthreads();
    float* dst = out + ((size_t)b * VV + v0) * TT;
#pragma unroll
    for (int l = 0; l < 32; l++) {
        int e = threadIdx.x + l * 256;
        int vi = e >> 6;
        int tt = e & 63;
        dst[(size_t)vi * TT + tt] = tile[vi][tt];
    }
}

// ---------------- host threefry ----------------
static void host_threefry(unsigned k0, unsigned k1, unsigned x0, unsigned x1,
                          unsigned& o0, unsigned& o1) {
    unsigned ks2 = k0 ^ k1 ^ 0x1BD11BDAu;
    x0 += k0; x1 += k1;
#define HTF_RND(r) { x0 += x1; x1 = (x1 << r) | (x1 >> (32 - r)); x1 ^= x0; }
    HTF_RND(13) HTF_RND(15) HTF_RND(26) HTF_RND(6)  x0 += k1;  x1 += ks2 + 1u;
    HTF_RND(17) HTF_RND(29) HTF_RND(16) HTF_RND(24) x0 += ks2; x1 += k0 + 2u;
    HTF_RND(13) HTF_RND(15) HTF_RND(26) HTF_RND(6)  x0 += k0;  x1 += k1 + 3u;
    HTF_RND(17) HTF_RND(29) HTF_RND(16) HTF_RND(24) x0 += k1;  x1 += ks2 + 4u;
    HTF_RND(13) HTF_RND(15) HTF_RND(26) HTF_RND(6)  x0 += ks2; x1 += k0 + 5u;
#undef HTF_RND
    o0 = x0; o1 = x1;
}

extern "C" void kernel_launch(void* const* d_in, const int* in_sizes, int n_in,
                              void* d_out, int out_size) {
    const float* condition = (const float*)d_in[0];
    const float* Wh    = (const float*)d_in[1];
    const float* bh    = (const float*)d_in[2];
    const float* Wc    = (const float*)d_in[3];
    const float* bc    = (const float*)d_in[4];
    const float* embed = (const float*)d_in[5];
    const float* Wih   = (const float*)d_in[6];
    const float* bih   = (const float*)d_in[7];
    const float* Whh   = (const float*)d_in[8];
    const float* bhh   = (const float*)d_in[9];
    const float* Wout  = (const float*)d_in[10];
    const float* bout  = (const float*)d_in[11];

    float* stage;
    unsigned long long* best;
    cudaGetSymbolAddress((void**)&stage, g_stage);
    cudaGetSymbolAddress((void**)&best, g_best);

    const long long n_cap = (long long)BB * TT;
    const long long n_log = (long long)BB * VV * TT;
    float* cap_f = nullptr;
    int*   cap_i = nullptr;
    float* log_out = nullptr;
    long long osz = (long long)out_size;
    if (osz == n_cap + n_log) {
        cap_f = (float*)d_out;
        log_out = (float*)d_out + n_cap;
    } else if (osz == n_log) {
        log_out = (float*)d_out;
    } else if (osz == n_cap) {
        cap_i = (int*)d_out;
    } else {
        cap_f = (float*)d_out;
        log_out = (float*)d_out + n_cap;
    }

    cudaFuncSetAttribute(logits_kernel,
                         cudaFuncAttributeMaxDynamicSharedMemorySize, SMEM_MMA);
    cudaFuncSetAttribute(lstm_mma_kernel,
                         cudaFuncAttributeMaxDynamicSharedMemorySize, SMEM_MMA);

    convert_kernel<<<VV * HH / 1024, 256>>>(Wout);
    convert_lstm_kernel<<<MROWS * EE / 1024, 256>>>(Wih, EE, 0);
    convert_lstm_kernel<<<MROWS * HH / 1024, 256>>>(Whh, HH, EE);
    init_kernel<<<128, 256>>>(condition, Wh, bh, Wc, bc);

    for (int t = 0; t < TT; t++) {
        gather_kernel<<<64, 256>>>(embed, t);
        dim3 ggrid(MROWS / 128, SPLITK);
        lstm_mma_kernel<<<ggrid, 256, SMEM_MMA>>>();
        cell_kernel<<<64, 128>>>(bih, bhh);
        unsigned o0, o1;
        host_threefry(0u, 42u, 0u, (unsigned)t, o0, o1);
        logits_kernel<<<NBLK_LOG, 256, SMEM_MMA>>>(bout, stage, best, t, o0, o1);
    }
    caption_kernel<<<8, 256>>>(cap_f, cap_i);
    if (log_out) transpose_kernel<<<8000, 256>>>(stage, log_out);
}